// round 11
// baseline (speedup 1.0000x reference)
#include <cuda_runtime.h>
#include <math.h>

#define HD     128
#define NB     32          // batch
#define NQ     32          // q heads
#define NKV    8           // kv heads
#define REP    4           // NQ / NKV
#define DIM    4096
#define TSEQ   2048
#define NCHUNK 16
#define CHLEN  128         // TSEQ / NCHUNK
#define QKV_ROWS (DIM + 2*NKV*HD)   // 6144

// ---------------- scratch (no allocations allowed) ----------------
__device__ __align__(16) float g_xT[DIM*NB];                 // packed [k>>2][b][4]
__device__ __align__(16) float g_qkv[QKV_ROWS*NB];           // [row][b]
__device__ __align__(16) float g_pm[NB*NKV*REP*NCHUNK];
__device__ __align__(16) float g_pl[NB*NKV*REP*NCHUNK];
__device__ __align__(16) float g_pacc[NB*NKV*REP*NCHUNK*HD]; // 8MB
__device__ __align__(16) float g_attT[DIM*NB];               // packed [row>>2][b][4]

// ---------------- f32x2 helpers (sm_100+) ----------------
typedef unsigned long long ull;
__device__ __forceinline__ ull pk2(float lo, float hi) {
    ull r; asm("mov.b64 %0,{%1,%2};" : "=l"(r) : "f"(lo), "f"(hi)); return r;
}
__device__ __forceinline__ void upk2(float& lo, float& hi, ull v) {
    asm("mov.b64 {%0,%1},%2;" : "=f"(lo), "=f"(hi) : "l"(v));
}
__device__ __forceinline__ void fma2(ull& d, ull a, ull b) {
    asm("fma.rn.f32x2 %0,%1,%2,%0;" : "+l"(d) : "l"(a), "l"(b));
}

// ---------------- cp.async helpers ----------------
__device__ __forceinline__ void cp16(void* smem, const void* gmem) {
    unsigned s = (unsigned)__cvta_generic_to_shared(smem);
    asm volatile("cp.async.cg.shared.global [%0],[%1],16;\n" :: "r"(s), "l"(gmem));
}
__device__ __forceinline__ void cp_commit() {
    asm volatile("cp.async.commit_group;\n" ::: "memory");
}
template<int N> __device__ __forceinline__ void cp_wait() {
    asm volatile("cp.async.wait_group %0;\n" :: "n"(N) : "memory");
}

// ---------------- transpose x [32][4096] -> xT packed [k/4][b][4] ----------------
__global__ void k_transpose(const float* __restrict__ x) {
    int t = blockIdx.x * blockDim.x + threadIdx.x;
    if (t < (DIM / 4) * NB) {
        int b  = t & 31;
        int k4 = t >> 5;
        float4 v = *(const float4*)(x + (size_t)b * DIM + k4 * 4);
        *(float4*)&g_xT[(size_t)k4 * (NB * 4) + b * 4] = v;
    }
}

// ---------------- skinny GEMM (f32x2, cp.async 3-stage pipeline) + fused RoPE ----------------
// lane = batch. Warp owns 2 consecutive rows. 256 threads, 16 rows/block, 64-k tiles.
// SRC: 0 -> g_xT, 1 -> g_attT (packed [k/4][b][4]).
// DST: 0 -> g_qkv[(off+row)*NB+lane], 1 -> dOut[lane*DIM+row]
template<int SRC, int DST>
__global__ void __launch_bounds__(256) k_gemm(
    const float* __restrict__ W0, const float* __restrict__ W1, int splitRow,
    float* __restrict__ dOut, int outRowOff, int ropeLimit,
    const float* __restrict__ fc, const float* __restrict__ fs)
{
    const int ROWS = 16, KT = 64, NT = DIM / KT;   // 64 tiles
    __shared__ __align__(16) float Wsh[3][ROWS][KT];   // 12KB

    const int tid  = threadIdx.x;
    const int lane = tid & 31;                 // batch
    const int wid  = tid >> 5;
    const int rowBlk = blockIdx.x * ROWS;

    const float* __restrict__ xT = (SRC == 0) ? g_xT : g_attT;

    // staging assignment: thread -> one float4 per tile
    const int lr  = tid >> 4;                  // local row 0..15
    const int cc4 = (tid & 15) << 2;           // col 0..60 step 4
    int grow = rowBlk + lr;
    const float* wrow = ((grow < splitRow)
        ? (W0 + (size_t)grow * DIM)
        : (W1 + (size_t)(grow - splitRow) * DIM)) + cc4;

    ull acc2[2];
    acc2[0] = pk2(0.f, 0.f);
    acc2[1] = pk2(0.f, 0.f);

    // prologue: stage tiles 0,1
    cp16(&Wsh[0][lr][cc4], wrow + 0 * KT); cp_commit();
    cp16(&Wsh[1][lr][cc4], wrow + 1 * KT); cp_commit();

    const float* xbase = xT + lane * 4;

    for (int t = 0; t < NT; t++) {
        cp_wait<1>();          // tile t staged
        __syncthreads();       // also fences: all consumed buf (t-1)%3 before restage below
        const int buf = t % 3;
        const float* xp = xbase + (size_t)(t * (KT / 4)) * (NB * 4);
#pragma unroll
        for (int kk = 0; kk < KT; kk += 4) {
            float4 xv = *(const float4*)(xp + (kk >> 2) * (NB * 4));
            ull x01 = pk2(xv.x, xv.y);
            ull x23 = pk2(xv.z, xv.w);
#pragma unroll
            for (int r = 0; r < 2; r++) {
                float4 w4 = *(const float4*)&Wsh[buf][wid * 2 + r][kk];  // broadcast
                fma2(acc2[r], pk2(w4.x, w4.y), x01);
                fma2(acc2[r], pk2(w4.z, w4.w), x23);
            }
        }
        if (t + 2 < NT) {
            cp16(&Wsh[(t + 2) % 3][lr][cc4], wrow + (size_t)(t + 2) * KT);
        }
        cp_commit();
    }

    float a0, a1;
    { float lo, hi; upk2(lo, hi, acc2[0]); a0 = lo + hi; }
    { float lo, hi; upk2(lo, hi, acc2[1]); a1 = lo + hi; }

    // fused RoPE on the (even,odd) row pair + store
    int row0 = rowBlk + wid * 2;
    if (row0 < ropeLimit) {
        int ii = (row0 & (HD - 1)) >> 1;
        float cchi = fc[ii], ss = fs[ii];
        float n0 = a0 * cchi - a1 * ss;
        float n1 = a0 * ss + a1 * cchi;
        a0 = n0; a1 = n1;
    }
    if (DST == 0) {
        g_qkv[(size_t)(outRowOff + row0)     * NB + lane] = a0;
        g_qkv[(size_t)(outRowOff + row0 + 1) * NB + lane] = a1;
    } else {
        dOut[(size_t)lane * DIM + row0]     = a0;
        dOut[(size_t)lane * DIM + row0 + 1] = a1;
    }
}

// ---------------- split-KV attention: block = (chunk, g, b), 128 threads ----------------
// lane = (tq = lane&3 token-in-quad, dg = lane>>2 d-group of 16). Warp owns 32 tokens.
__global__ void __launch_bounds__(128) k_attn(const float* __restrict__ cache_k,
                                              const float* __restrict__ cache_v)
{
    const int c   = blockIdx.x;    // chunk 0..15
    const int g   = blockIdx.y;
    const int b   = blockIdx.z;
    const int tid = threadIdx.x, lane = tid & 31, wid = tid >> 5;
    const int tq  = lane & 3, dg = lane >> 2;

    __shared__ __align__(16) float Ssh[REP][CHLEN];    // 2KB
    __shared__ __align__(16) float Red[4][REP][HD];    // 8KB
    __shared__ __align__(16) float Kn[HD];
    __shared__ __align__(16) float Vn[HD];

    const float scale = 0.088388347648318447f;  // 1/sqrt(128)

    Kn[tid] = g_qkv[(size_t)(DIM + g * HD + tid) * NB + b];
    Vn[tid] = g_qkv[(size_t)(DIM + NKV * HD + g * HD + tid) * NB + b];

    float qv[REP][16];
#pragma unroll
    for (int r = 0; r < REP; r++) {
        int rowBase = (g * REP + r) * HD + dg * 16;
#pragma unroll
        for (int j = 0; j < 16; j++)
            qv[r][j] = g_qkv[(size_t)(rowBase + j) * NB + b] * scale;
    }
    __syncthreads();

    const size_t strT   = (size_t)NKV * HD;                  // 1024
    const size_t baseBG = (size_t)b * TSEQ * strT + (size_t)g * HD;
    const bool special  = (c == NCHUNK - 1) && (wid == 3);   // contains t = 2047
    const int  tWarp    = c * CHLEN + wid * 32;

    // ---- scores ----
    const int nIter = special ? 7 : 8;
#pragma unroll 2
    for (int i = 0; i < nIter; i++) {
        int t = tWarp + i * 4 + tq;
        const float* kp = cache_k + baseBG + (size_t)t * strT + dg * 16;
        float4 ka = *(const float4*)(kp + 0);
        float4 kb = *(const float4*)(kp + 4);
        float4 kc = *(const float4*)(kp + 8);
        float4 kd = *(const float4*)(kp + 12);
        float p[REP];
#pragma unroll
        for (int r = 0; r < REP; r++) {
            float s = qv[r][0] * ka.x;
            s = fmaf(qv[r][1], ka.y, s);  s = fmaf(qv[r][2], ka.z, s);  s = fmaf(qv[r][3], ka.w, s);
            s = fmaf(qv[r][4], kb.x, s);  s = fmaf(qv[r][5], kb.y, s);  s = fmaf(qv[r][6], kb.z, s);  s = fmaf(qv[r][7], kb.w, s);
            s = fmaf(qv[r][8], kc.x, s);  s = fmaf(qv[r][9], kc.y, s);  s = fmaf(qv[r][10], kc.z, s); s = fmaf(qv[r][11], kc.w, s);
            s = fmaf(qv[r][12], kd.x, s); s = fmaf(qv[r][13], kd.y, s); s = fmaf(qv[r][14], kd.z, s); s = fmaf(qv[r][15], kd.w, s);
            p[r] = s;
        }
#pragma unroll
        for (int off = 4; off <= 16; off <<= 1) {
#pragma unroll
            for (int r = 0; r < REP; r++) p[r] += __shfl_xor_sync(0xffffffffu, p[r], off);
        }
        if (dg == 0) {
            int tl = wid * 32 + i * 4 + tq;
#pragma unroll
            for (int r = 0; r < REP; r++) Ssh[r][tl] = p[r];
        }
    }
    if (special) {   // tokens 2044..2047; tq==3 uses staged new k
        float4 ka, kb, kc, kd;
        if (tq == 3) {
            ka = *(const float4*)&Kn[dg * 16 + 0];
            kb = *(const float4*)&Kn[dg * 16 + 4];
            kc = *(const float4*)&Kn[dg * 16 + 8];
            kd = *(const float4*)&Kn[dg * 16 + 12];
        } else {
            int t = tWarp + 28 + tq;
            const float* kp = cache_k + baseBG + (size_t)t * strT + dg * 16;
            ka = *(const float4*)(kp + 0);
            kb = *(const float4*)(kp + 4);
            kc = *(const float4*)(kp + 8);
            kd = *(const float4*)(kp + 12);
        }
        float p[REP];
#pragma unroll
        for (int r = 0; r < REP; r++) {
            float s = qv[r][0] * ka.x;
            s = fmaf(qv[r][1], ka.y, s);  s = fmaf(qv[r][2], ka.z, s);  s = fmaf(qv[r][3], ka.w, s);
            s = fmaf(qv[r][4], kb.x, s);  s = fmaf(qv[r][5], kb.y, s);  s = fmaf(qv[r][6], kb.z, s);  s = fmaf(qv[r][7], kb.w, s);
            s = fmaf(qv[r][8], kc.x, s);  s = fmaf(qv[r][9], kc.y, s);  s = fmaf(qv[r][10], kc.z, s); s = fmaf(qv[r][11], kc.w, s);
            s = fmaf(qv[r][12], kd.x, s); s = fmaf(qv[r][13], kd.y, s); s = fmaf(qv[r][14], kd.z, s); s = fmaf(qv[r][15], kd.w, s);
            p[r] = s;
        }
#pragma unroll
        for (int off = 4; off <= 16; off <<= 1) {
#pragma unroll
            for (int r = 0; r < REP; r++) p[r] += __shfl_xor_sync(0xffffffffu, p[r], off);
        }
        if (dg == 0) {
            int tl = wid * 32 + 28 + tq;
#pragma unroll
            for (int r = 0; r < REP; r++) Ssh[r][tl] = p[r];
        }
    }
    __syncthreads();

    // ---- partial softmax: warp wid handles rep r = wid ----
    {
        int r = wid;
        float v[4];
        float m = -1e30f;
#pragma unroll
        for (int j = 0; j < 4; j++) { v[j] = Ssh[r][lane + j * 32]; m = fmaxf(m, v[j]); }
#pragma unroll
        for (int off = 16; off > 0; off >>= 1) m = fmaxf(m, __shfl_xor_sync(0xffffffffu, m, off));
        float l = 0.f;
#pragma unroll
        for (int j = 0; j < 4; j++) { float e = __expf(v[j] - m); l += e; Ssh[r][lane + j * 32] = e; }
#pragma unroll
        for (int off = 16; off > 0; off >>= 1) l += __shfl_xor_sync(0xffffffffu, l, off);
        if (lane == 0) {
            int idx = ((b * NKV + g) * REP + r) * NCHUNK + c;
            g_pm[idx] = m;
            g_pl[idx] = l;
        }
    }
    __syncthreads();

    // ---- AV: warp owns 32 tokens, lane covers d = lane*4..+3 ----
    float4 a4[REP];
#pragma unroll
    for (int r = 0; r < REP; r++) { a4[r].x = a4[r].y = a4[r].z = a4[r].w = 0.f; }
    const int nAV = special ? 31 : 32;
#pragma unroll 8
    for (int i = 0; i < nAV; i++) {
        int tl = wid * 32 + i;
        int t  = c * CHLEN + tl;
        float4 v4 = *(const float4*)(cache_v + baseBG + (size_t)t * strT + lane * 4);
#pragma unroll
        for (int r = 0; r < REP; r++) {
            float p = Ssh[r][tl];
            a4[r].x = fmaf(p, v4.x, a4[r].x);
            a4[r].y = fmaf(p, v4.y, a4[r].y);
            a4[r].z = fmaf(p, v4.z, a4[r].z);
            a4[r].w = fmaf(p, v4.w, a4[r].w);
        }
    }
    if (special) {
        float4 v4 = *(const float4*)&Vn[lane * 4];
#pragma unroll
        for (int r = 0; r < REP; r++) {
            float p = Ssh[r][CHLEN - 1];
            a4[r].x = fmaf(p, v4.x, a4[r].x);
            a4[r].y = fmaf(p, v4.y, a4[r].y);
            a4[r].z = fmaf(p, v4.z, a4[r].z);
            a4[r].w = fmaf(p, v4.w, a4[r].w);
        }
    }
#pragma unroll
    for (int r = 0; r < REP; r++) *(float4*)&Red[wid][r][lane * 4] = a4[r];
    __syncthreads();
    {
        int r = wid;
        float4 s0 = *(const float4*)&Red[0][r][lane * 4];
        float4 s1 = *(const float4*)&Red[1][r][lane * 4];
        float4 s2 = *(const float4*)&Red[2][r][lane * 4];
        float4 s3 = *(const float4*)&Red[3][r][lane * 4];
        float4 o;
        o.x = s0.x + s1.x + s2.x + s3.x;
        o.y = s0.y + s1.y + s2.y + s3.y;
        o.z = s0.z + s1.z + s2.z + s3.z;
        o.w = s0.w + s1.w + s2.w + s3.w;
        int idx = ((b * NKV + g) * REP + r) * NCHUNK + c;
        *(float4*)&g_pacc[(size_t)idx * HD + lane * 4] = o;
    }
}

// ---------------- combine 16 split-KV partials -> attT (packed layout) ----------------
__global__ void __launch_bounds__(128) k_combine() {
    int b  = blockIdx.x;
    int qh = blockIdx.y;          // qh = g*4 + r
    int base = (b * (NKV * REP) + qh) * NCHUNK;
    float m[NCHUNK];
    float M = -1e30f;
#pragma unroll
    for (int c = 0; c < NCHUNK; c++) { m[c] = g_pm[base + c]; M = fmaxf(M, m[c]); }
    float w[NCHUNK];
    float L = 0.f;
#pragma unroll
    for (int c = 0; c < NCHUNK; c++) { w[c] = __expf(m[c] - M); L = fmaf(w[c], g_pl[base + c], L); }
    float inv = 1.f / L;
    int d = threadIdx.x;
    float val = 0.f;
#pragma unroll
    for (int c = 0; c < NCHUNK; c++)
        val = fmaf(w[c], g_pacc[(size_t)(base + c) * HD + d], val);
    int row = qh * HD + d;
    g_attT[(size_t)(row >> 2) * (NB * 4) + b * 4 + (row & 3)] = val * inv;
}

// ---------------- launch ----------------
extern "C" void kernel_launch(void* const* d_in, const int* in_sizes, int n_in,
                              void* d_out, int out_size) {
    const float* x  = (const float*)d_in[0];
    const float* wq = (const float*)d_in[1];
    const float* wk = (const float*)d_in[2];
    const float* wv = (const float*)d_in[3];
    const float* wo = (const float*)d_in[4];
    const float* fc = (const float*)d_in[5];
    const float* fs = (const float*)d_in[6];
    const float* ck = (const float*)d_in[7];
    const float* cv = (const float*)d_in[8];
    float* out = (float*)d_out;

    // 0: transpose
    k_transpose<<<128, 256>>>(x);
    // 1: wq rows 0..2047 (RoPE all) -> g_qkv rows 0..2047
    k_gemm<0, 0><<<128, 256>>>(wq, wq, 1 << 30, nullptr, 0, 2048, fc, fs);
    // 2: wq rows 2048..4095 (RoPE all; (row&127) identical for local rows)
    k_gemm<0, 0><<<128, 256>>>(wq + (size_t)2048 * DIM, wq + (size_t)2048 * DIM,
                               1 << 30, nullptr, 2048, 2048, fc, fs);
    // 3: wk+wv fused (2048 rows, RoPE on first 1024 = k) -> g_qkv rows 4096..6143
    k_gemm<0, 0><<<128, 256>>>(wk, wv, 1024, nullptr, DIM, 1024, fc, fs);
    // 4: attention, single launch, 16 chunks
    k_attn<<<dim3(NCHUNK, NKV, NB), 128>>>(ck, cv);
    // 5: combine
    k_combine<<<dim3(NB, NQ), 128>>>();
    // 6: wo
    k_gemm<1, 1><<<256, 256>>>(wo, wo, 1 << 30, out, 0, 0, fc, fs);
}